// round 1
// baseline (speedup 1.0000x reference)
#include <cuda_runtime.h>
#include <cstdint>
#include <math.h>

#define BB 2048
#define NN 200
#define HH 128

// ---- shared memory layout (floats) ----
// WT   : [128][132] transposed W   (WT[h][o] = W[o][h])
#define WT_OFF   0
// bias : [128]
#define BIAS_OFF 16896
// XT   : [128][68] transposed x-chunk (XT[h][r])
#define XT_OFF   17024
// Esm  : [200][132] projected embeddings (row pad 132, 16B-aligned rows)
#define E_OFF    25728
// aux
#define CX_OFF   52128
#define CY_OFF   52328
#define DEM_OFF  52528
#define VIS_OFF  52728   // 200 ints
#define RED_OFF  52928   // 8 floats
#define REDI_OFF 52936   // 8 ints
#define NXT_OFF  52944   // 1 int
#define SMEM_FLOATS 52960
#define SMEM_BYTES  (SMEM_FLOATS * 4)

__device__ __forceinline__ float neg_inf() { return __int_as_float(0xff800000); }

__global__ void k_zero(float* __restrict__ out, int n) {
    int i = blockIdx.x * blockDim.x + threadIdx.x;
    if (i < n) out[i] = 0.0f;
}

__global__ void __launch_bounds__(256, 1)
k_fused(const float* __restrict__ x, const float* __restrict__ W,
        const float* __restrict__ bias, const float* __restrict__ coords,
        const float* __restrict__ demands, const float* __restrict__ capacity,
        const int* __restrict__ nsteps, float* __restrict__ out) {
    extern __shared__ float sm[];
    const int tid = threadIdx.x;
    const int b = blockIdx.x;
    const int tx = tid & 15;   // o / j dimension
    const int ty = tid >> 4;   // r / i dimension

    // ---------------- prologue: W^T, bias, coords, demands, visited ----------------
    for (int idx = tid; idx < HH * HH; idx += 256) {
        int o = idx >> 7, h = idx & 127;
        sm[WT_OFF + h * 132 + o] = W[idx];
    }
    if (tid < HH) sm[BIAS_OFF + tid] = bias[tid];
    {
        const float* cb = coords + (size_t)b * NN * 2;
        const float* db = demands + (size_t)b * NN;
        for (int n = tid; n < NN; n += 256) {
            sm[CX_OFF + n] = cb[2 * n];
            sm[CY_OFF + n] = cb[2 * n + 1];
            sm[DEM_OFF + n] = db[n];
            ((int*)(sm + VIS_OFF))[n] = 0;
        }
    }
    __syncthreads();

    // ---------------- projection: E[n][o] = sum_h x[b][n][h] * W[o][h] + b[o] ------
    const float* xb = x + (size_t)b * NN * HH;

    // 3 full chunks of 64 rows
    for (int c = 0; c < 3; c++) {
        const int r0 = c * 64;
        for (int idx = tid; idx < 64 * HH; idx += 256) {
            int r = idx >> 7, h = idx & 127;
            sm[XT_OFF + h * 68 + r] = xb[(size_t)(r0 + r) * HH + h];
        }
        __syncthreads();

        float acc[4][8];
        #pragma unroll
        for (int ii = 0; ii < 4; ii++)
            #pragma unroll
            for (int jj = 0; jj < 8; jj++) acc[ii][jj] = 0.0f;

        #pragma unroll 2
        for (int h = 0; h < HH; h++) {
            float a[4], w[8];
            #pragma unroll
            for (int ii = 0; ii < 4; ii++) a[ii] = sm[XT_OFF + h * 68 + ty + 16 * ii];
            #pragma unroll
            for (int jj = 0; jj < 8; jj++) w[jj] = sm[WT_OFF + h * 132 + tx + 16 * jj];
            #pragma unroll
            for (int ii = 0; ii < 4; ii++)
                #pragma unroll
                for (int jj = 0; jj < 8; jj++)
                    acc[ii][jj] = fmaf(a[ii], w[jj], acc[ii][jj]);
        }
        #pragma unroll
        for (int ii = 0; ii < 4; ii++) {
            int n = r0 + ty + 16 * ii;
            #pragma unroll
            for (int jj = 0; jj < 8; jj++) {
                int o = tx + 16 * jj;
                sm[E_OFF + n * 132 + o] = acc[ii][jj] + sm[BIAS_OFF + o];
            }
        }
        __syncthreads();
    }

    // tail chunk: rows 192..199 (8 rows)
    {
        for (int idx = tid; idx < 8 * HH; idx += 256) {
            int r = idx >> 7, h = idx & 127;
            sm[XT_OFF + h * 68 + r] = xb[(size_t)(192 + r) * HH + h];
        }
        __syncthreads();
        if (ty < 8) {
            float acc8[8];
            #pragma unroll
            for (int jj = 0; jj < 8; jj++) acc8[jj] = 0.0f;
            #pragma unroll 2
            for (int h = 0; h < HH; h++) {
                float a = sm[XT_OFF + h * 68 + ty];
                #pragma unroll
                for (int jj = 0; jj < 8; jj++)
                    acc8[jj] = fmaf(a, sm[WT_OFF + h * 132 + tx + 16 * jj], acc8[jj]);
            }
            int n = 192 + ty;
            #pragma unroll
            for (int jj = 0; jj < 8; jj++) {
                int o = tx + 16 * jj;
                sm[E_OFF + n * 132 + o] = acc8[jj] + sm[BIAS_OFF + o];
            }
        }
        __syncthreads();
    }

    // ---------------- greedy routing with depot fixed-point early exit -------------
    const int T = nsteps ? nsteps[0] : 180;
    const int t = tid;                    // thread t <-> node t
    const float cap = capacity[b];
    float rem = cap;
    int cur = 0;

    float myd = 0.0f, mycx = 0.0f, mycy = 0.0f;
    if (t < NN) {
        myd = sm[DEM_OFF + t];
        mycx = sm[CX_OFF + t];
        mycy = sm[CY_OFF + t];
    }

    for (int step = 0; step < T; step++) {
        float s = neg_inf();
        if (t < NN) {
            const float* Er = sm + E_OFF + t * 132;
            const float* Qr = sm + E_OFF + cur * 132;
            float s0 = 0.f, s1 = 0.f, s2 = 0.f, s3 = 0.f;
            #pragma unroll
            for (int h = 0; h < HH; h += 4) {
                float4 e = *(const float4*)(Er + h);
                float4 q = *(const float4*)(Qr + h);
                s0 = fmaf(e.x, q.x, s0);
                s1 = fmaf(e.y, q.y, s1);
                s2 = fmaf(e.z, q.z, s2);
                s3 = fmaf(e.w, q.w, s3);
            }
            float sim = (s0 + s1) + (s2 + s3);
            float dx = mycx - sm[CX_OFF + cur];
            float dy = mycy - sm[CY_OFF + cur];
            s = sim - 0.1f * sqrtf(dx * dx + dy * dy);
            int v = ((const int*)(sm + VIS_OFF))[t];
            if (t != 0 && (v || (myd > rem))) s = neg_inf();
        }
        // warp argmax with first-index tie-break (matches jnp.argmax)
        float bv = s;
        int bi = t;
        #pragma unroll
        for (int off = 16; off > 0; off >>= 1) {
            float ov = __shfl_xor_sync(0xffffffffu, bv, off);
            int oi = __shfl_xor_sync(0xffffffffu, bi, off);
            if (ov > bv || (ov == bv && oi < bi)) { bv = ov; bi = oi; }
        }
        if ((tid & 31) == 0) {
            sm[RED_OFF + (tid >> 5)] = bv;
            ((int*)(sm + REDI_OFF))[tid >> 5] = bi;
        }
        __syncthreads();
        if (tid == 0) {
            float Bv = sm[RED_OFF];
            int Bi = ((int*)(sm + REDI_OFF))[0];
            #pragma unroll
            for (int w = 1; w < 8; w++) {
                float v = sm[RED_OFF + w];
                int i2 = ((int*)(sm + REDI_OFF))[w];
                if (v > Bv || (v == Bv && i2 < Bi)) { Bv = v; Bi = i2; }
            }
            ((int*)(sm + NXT_OFF))[0] = Bi;
            ((int*)(sm + VIS_OFF))[Bi] = 1;
            out[(size_t)b * T + step] = (float)Bi;
        }
        __syncthreads();
        int nxt = ((int*)(sm + NXT_OFF))[0];
        float dn = sm[DEM_OFF + nxt];
        rem = (nxt == 0) ? cap : (rem - dn);
        int prev = cur;
        cur = nxt;
        // depot fixed point: state repeats exactly -> all remaining actions are 0,
        // and the output buffer is already zeroed.
        if (prev == 0 && nxt == 0) break;
    }
}

extern "C" void kernel_launch(void* const* d_in, const int* in_sizes, int n_in,
                              void* d_out, int out_size) {
    const float* x        = (const float*)d_in[0];
    const float* W        = (const float*)d_in[1];
    const float* bias     = (const float*)d_in[2];
    const float* coords   = (const float*)d_in[3];
    const float* demands  = (const float*)d_in[4];
    const float* capacity = (const float*)d_in[5];
    const int*   nsteps   = (n_in > 6) ? (const int*)d_in[6] : nullptr;
    float* out = (float*)d_out;

    cudaFuncSetAttribute(k_fused, cudaFuncAttributeMaxDynamicSharedMemorySize, SMEM_BYTES);

    int zgrid = (out_size + 255) / 256;
    k_zero<<<zgrid, 256>>>(out, out_size);
    k_fused<<<BB, 256, SMEM_BYTES>>>(x, W, bias, coords, demands, capacity, nsteps, out);
}

// round 3
// speedup vs baseline: 8.4828x; 8.4828x over previous
#include <cuda_runtime.h>
#include <cstdint>
#include <math.h>

#define BB 2048
#define NN 200
#define HH 128

// ---- dynamic shared memory layout (float units) ----
#define XS_OFF   0            // [200][132] x rows, pad 132 (16B-aligned, conflict-free f4)
#define CX_OFF   26400        // 200
#define CY_OFF   26600        // 200
#define DEM_OFF  26800        // 200
#define VIS_OFF  27000        // 200 ints
#define Q_OFF    27200        // 128
#define V_OFF    27328        // 128
#define VP_OFF   27456        // 128 (partial for v)
#define RED_OFF  27584        // 8 floats
#define REDI_OFF 27592        // 8 ints
#define NXT_OFF  27600        // 1 int
#define SMEM_FLOATS 27608
#define SMEM_BYTES  (SMEM_FLOATS * 4)   // 110,432 B -> 2 CTAs/SM

__device__ __forceinline__ float neg_inf() { return __int_as_float(0xff800000); }

__global__ void k_zero(float* __restrict__ out, int n) {
    int i = blockIdx.x * blockDim.x + threadIdx.x;
    if (i < n) out[i] = 0.0f;
}

__global__ void __launch_bounds__(256, 2)
k_route(const float* __restrict__ x, const float* __restrict__ W,
        const float* __restrict__ bias, const float* __restrict__ coords,
        const float* __restrict__ demands, const float* __restrict__ capacity,
        const int* __restrict__ nsteps, float* __restrict__ out) {
    extern __shared__ float sm[];
    const int tid  = threadIdx.x;
    const int b    = blockIdx.x;
    const int lane = tid & 31;
    const int wid  = tid >> 5;

    // ---------------- stage x_b (coalesced f4), coords, demands, visited ----------
    {
        const float4* xb4 = (const float4*)(x + (size_t)b * NN * HH);
        for (int idx = tid; idx < NN * 32; idx += 256) {
            int n = idx >> 5, j = idx & 31;             // 32 float4 per row
            *(float4*)(sm + XS_OFF + n * 132 + j * 4) = xb4[(size_t)n * 32 + j];
        }
        const float* cb = coords + (size_t)b * NN * 2;
        const float* db = demands + (size_t)b * NN;
        for (int n = tid; n < NN; n += 256) {
            sm[CX_OFF + n] = cb[2 * n];
            sm[CY_OFF + n] = cb[2 * n + 1];
            sm[DEM_OFF + n] = db[n];
            ((int*)(sm + VIS_OFF))[n] = 0;
        }
    }
    __syncthreads();

    const int T = nsteps ? nsteps[0] : 180;
    const int t = tid;
    const float cap = capacity[b];
    float rem = cap;
    int cur = 0;

    float myd = 0.f, mycx = 0.f, mycy = 0.f;
    if (t < NN) {
        myd  = sm[DEM_OFF + t];
        mycx = sm[CX_OFF + t];
        mycy = sm[CY_OFF + t];
    }

    for (int step = 0; step < T; step++) {
        // ---- (a) q[o] = sum_h W[o][h] * x[cur][h] + bias[o]  (warp per row group)
        {
            float4 xc = *(const float4*)(sm + XS_OFF + cur * 132 + lane * 4);
            #pragma unroll
            for (int r = 0; r < 16; r++) {
                int o = wid + r * 8;                    // 8 warps cover 128 rows
                float4 w4 = *(const float4*)(W + (size_t)o * HH + lane * 4);
                float p = fmaf(w4.x, xc.x, fmaf(w4.y, xc.y,
                          fmaf(w4.z, xc.z, w4.w * xc.w)));
                #pragma unroll
                for (int off = 16; off > 0; off >>= 1)
                    p += __shfl_xor_sync(0xffffffffu, p, off);
                if (lane == 0) sm[Q_OFF + o] = p + bias[o];
            }
        }
        __syncthreads();

        // ---- (b) v[h] = sum_o W[o][h] * q[o]   (coalesced column sweep, o split in 2)
        {
            int h = t & 127, half = t >> 7;             // half in {0,1}
            float acc = 0.f;
            const float* Wp = W + (size_t)(half * 64) * HH + h;
            const float* qp = sm + Q_OFF + half * 64;
            #pragma unroll 8
            for (int o = 0; o < 64; o++)
                acc = fmaf(Wp[(size_t)o * HH], qp[o], acc);
            if (half == 0) sm[V_OFF + h] = acc;
            else           sm[VP_OFF + h] = acc;
        }
        __syncthreads();
        if (t < 128) sm[V_OFF + t] += sm[VP_OFF + t];
        __syncthreads();

        // ---- (d) scores + masked argmax (b.q constant dropped: argmax-invariant)
        float s = neg_inf();
        if (t < NN) {
            const float* Xr = sm + XS_OFF + t * 132;
            const float* Vr = sm + V_OFF;
            float s0 = 0.f, s1 = 0.f, s2 = 0.f, s3 = 0.f;
            #pragma unroll
            for (int h = 0; h < HH; h += 4) {
                float4 e = *(const float4*)(Xr + h);
                float4 v = *(const float4*)(Vr + h);
                s0 = fmaf(e.x, v.x, s0);
                s1 = fmaf(e.y, v.y, s1);
                s2 = fmaf(e.z, v.z, s2);
                s3 = fmaf(e.w, v.w, s3);
            }
            float sim = (s0 + s1) + (s2 + s3);
            float dx = mycx - sm[CX_OFF + cur];
            float dy = mycy - sm[CY_OFF + cur];
            s = sim - 0.1f * sqrtf(dx * dx + dy * dy);
            int v = ((const int*)(sm + VIS_OFF))[t];
            if (t != 0 && (v || (myd > rem))) s = neg_inf();
        }
        // warp argmax, first-index tie-break (matches jnp.argmax)
        float bv = s; int bi = t;
        #pragma unroll
        for (int off = 16; off > 0; off >>= 1) {
            float ov = __shfl_xor_sync(0xffffffffu, bv, off);
            int   oi = __shfl_xor_sync(0xffffffffu, bi, off);
            if (ov > bv || (ov == bv && oi < bi)) { bv = ov; bi = oi; }
        }
        if (lane == 0) {
            sm[RED_OFF + wid] = bv;
            ((int*)(sm + REDI_OFF))[wid] = bi;
        }
        __syncthreads();
        if (tid == 0) {
            float Bv = sm[RED_OFF];
            int Bi = ((int*)(sm + REDI_OFF))[0];
            #pragma unroll
            for (int w = 1; w < 8; w++) {
                float v = sm[RED_OFF + w];
                int i2 = ((int*)(sm + REDI_OFF))[w];
                if (v > Bv || (v == Bv && i2 < Bi)) { Bv = v; Bi = i2; }
            }
            ((int*)(sm + NXT_OFF))[0] = Bi;
            ((int*)(sm + VIS_OFF))[Bi] = 1;
            out[(size_t)b * T + step] = (float)Bi;
        }
        __syncthreads();
        int nxt = ((int*)(sm + NXT_OFF))[0];
        float dn = sm[DEM_OFF + nxt];
        rem = (nxt == 0) ? cap : (rem - dn);
        int prev = cur;
        cur = nxt;
        // depot fixed point: identical state recurs -> remaining actions all 0,
        // and the output buffer is pre-zeroed.
        if (prev == 0 && nxt == 0) break;
    }
}

extern "C" void kernel_launch(void* const* d_in, const int* in_sizes, int n_in,
                              void* d_out, int out_size) {
    const float* x        = (const float*)d_in[0];
    const float* W        = (const float*)d_in[1];
    const float* bias     = (const float*)d_in[2];
    const float* coords   = (const float*)d_in[3];
    const float* demands  = (const float*)d_in[4];
    const float* capacity = (const float*)d_in[5];
    const int*   nsteps   = (n_in > 6) ? (const int*)d_in[6] : nullptr;
    float* out = (float*)d_out;

    cudaFuncSetAttribute(k_route, cudaFuncAttributeMaxDynamicSharedMemorySize, SMEM_BYTES);

    int zgrid = (out_size + 255) / 256;
    k_zero<<<zgrid, 256>>>(out, out_size);
    k_route<<<BB, 256, SMEM_BYTES>>>(x, W, bias, coords, demands, capacity, nsteps, out);
}